// round 1
// baseline (speedup 1.0000x reference)
#include <cuda_runtime.h>
#include <math.h>

// Problem constants (DividedAttention: b=8, f=16, n=196, dim=1024, H=16)
#define B_    8
#define F_    16
#define NTOK  196
#define NSEQ  3137          // 1 + F_*NTOK
#define DIM   1024
#define H_    16
#define DH    64
#define MROWS (B_ * NSEQ)   // 25096
#define QKVC  (3 * DIM)     // 3072

// Scratch (allowed: __device__ globals)
__device__ float g_qkv[(size_t)MROWS * QKVC];   // [b*N, 3072]
__device__ float g_att[(size_t)MROWS * DIM];    // [b*N, 1024] attention output (head-concat)

// ---------------------------------------------------------------------------
// SGEMM: C[M,N] = A[M,K] * B[N,K]^T (+ bias). A,B row-major, K-contiguous.
// 128x128 tile, BK=8, 8x8 per thread, 256 threads.
// ---------------------------------------------------------------------------
template <bool BIAS>
__global__ __launch_bounds__(256)
void sgemm_nt(int M, int N, int K,
              const float* __restrict__ A,
              const float* __restrict__ B,
              const float* __restrict__ bias,
              float* __restrict__ C) {
    const int BM = 128, BN = 128, BK = 8, TM = 8, TN = 8;
    __shared__ float As[BK][BM];
    __shared__ float Bs[BK][BN];

    int tid  = threadIdx.x;
    int row0 = blockIdx.y * BM;
    int col0 = blockIdx.x * BN;

    int ldRow = tid >> 1;          // 0..127
    int ldCol = (tid & 1) * 4;     // 0 or 4

    int ty = tid >> 4;             // 0..15
    int tx = tid & 15;             // 0..15

    float acc[TM][TN];
#pragma unroll
    for (int i = 0; i < TM; i++)
#pragma unroll
        for (int j = 0; j < TN; j++) acc[i][j] = 0.f;

    for (int k0 = 0; k0 < K; k0 += BK) {
        // Load A tile (row-guarded)
        int gr = row0 + ldRow;
        float4 av = make_float4(0.f, 0.f, 0.f, 0.f);
        if (gr < M) av = *(const float4*)(A + (size_t)gr * K + k0 + ldCol);
        As[ldCol + 0][ldRow] = av.x;
        As[ldCol + 1][ldRow] = av.y;
        As[ldCol + 2][ldRow] = av.z;
        As[ldCol + 3][ldRow] = av.w;
        // Load B tile (N is a multiple of 128 -> no guard)
        float4 bv = *(const float4*)(B + (size_t)(col0 + ldRow) * K + k0 + ldCol);
        Bs[ldCol + 0][ldRow] = bv.x;
        Bs[ldCol + 1][ldRow] = bv.y;
        Bs[ldCol + 2][ldRow] = bv.z;
        Bs[ldCol + 3][ldRow] = bv.w;
        __syncthreads();

#pragma unroll
        for (int kk = 0; kk < BK; kk++) {
            float ar[TM], br[TN];
#pragma unroll
            for (int i = 0; i < TM; i++) ar[i] = As[kk][ty * TM + i];
#pragma unroll
            for (int j = 0; j < TN; j++) br[j] = Bs[kk][tx * TN + j];
#pragma unroll
            for (int i = 0; i < TM; i++)
#pragma unroll
                for (int j = 0; j < TN; j++) acc[i][j] += ar[i] * br[j];
        }
        __syncthreads();
    }

    float bcol[TN];
#pragma unroll
    for (int j = 0; j < TN; j++)
        bcol[j] = BIAS ? bias[col0 + tx * TN + j] : 0.f;

#pragma unroll
    for (int i = 0; i < TM; i++) {
        int gr = row0 + ty * TM + i;
        if (gr < M) {
            float* cp = C + (size_t)gr * N + col0 + tx * TN;
#pragma unroll
            for (int j = 0; j < TN; j += 4) {
                float4 v;
                v.x = acc[i][j + 0] + bcol[j + 0];
                v.y = acc[i][j + 1] + bcol[j + 1];
                v.z = acc[i][j + 2] + bcol[j + 2];
                v.w = acc[i][j + 3] + bcol[j + 3];
                *(float4*)(cp + j) = v;
            }
        }
    }
}

// ---------------------------------------------------------------------------
// CLS attention: 1 query (token 0) per (b,h) over all NSEQ keys.
// grid = 128 blocks, 256 threads.
// ---------------------------------------------------------------------------
__global__ __launch_bounds__(256)
void cls_attn_kernel(const float* __restrict__ qkv, float* __restrict__ att) {
    int bh = blockIdx.x;
    int bi = bh >> 4;
    int hi = bh & 15;
    const float* base = qkv + (size_t)bi * NSEQ * QKVC;
    int qoff = hi * DH;
    int koff = DIM + hi * DH;
    int voff = 2 * DIM + hi * DH;

    __shared__ float qs[DH];
    __shared__ float s[NSEQ];
    __shared__ float red[256];

    int tid = threadIdx.x;
    if (tid < DH) qs[tid] = base[qoff + tid];   // token 0 q row
    __syncthreads();

    const float scale = 0.125f;   // 1/sqrt(64)
    for (int t = tid; t < NSEQ; t += 256) {
        const float* kp = base + (size_t)t * QKVC + koff;
        float acc = 0.f;
#pragma unroll
        for (int d = 0; d < DH; d++) acc += qs[d] * kp[d];
        s[t] = acc * scale;
    }
    __syncthreads();

    // block max
    float m = -INFINITY;
    for (int t = tid; t < NSEQ; t += 256) m = fmaxf(m, s[t]);
    red[tid] = m;
    __syncthreads();
    for (int st = 128; st > 0; st >>= 1) {
        if (tid < st) red[tid] = fmaxf(red[tid], red[tid + st]);
        __syncthreads();
    }
    m = red[0];
    __syncthreads();

    // exp + sum
    float l = 0.f;
    for (int t = tid; t < NSEQ; t += 256) {
        float p = __expf(s[t] - m);
        s[t] = p;
        l += p;
    }
    red[tid] = l;
    __syncthreads();
    for (int st = 128; st > 0; st >>= 1) {
        if (tid < st) red[tid] += red[tid + st];
        __syncthreads();
    }
    l = red[0];
    float inv = 1.f / l;

    if (tid < DH) {
        float o = 0.f;
        for (int t = 0; t < NSEQ; t++)
            o += s[t] * base[(size_t)t * QKVC + voff + tid];
        att[(size_t)bi * NSEQ * DIM + hi * DH + tid] = o * inv;
    }
}

// ---------------------------------------------------------------------------
// Divided attention: one block per (b,h,f). 196 queries, 197 keys (CLS + frame).
// K,V tiles in dynamic smem (197*64 floats each). One query row per thread,
// online softmax with conditional rescale (1 exp per key).
// ---------------------------------------------------------------------------
__global__ __launch_bounds__(256)
void div_attn_kernel(const float* __restrict__ qkv, float* __restrict__ att) {
    int unit = blockIdx.x;             // [0, 2048)
    int bh = unit >> 4;
    int fi = unit & 15;
    int bi = bh >> 4;
    int hi = bh & 15;
    const float* base = qkv + (size_t)bi * NSEQ * QKVC;
    int qoff = hi * DH;
    int koff = DIM + hi * DH;
    int voff = 2 * DIM + hi * DH;

    extern __shared__ float sh[];
    float* Ks = sh;                    // [197][64]
    float* Vs = sh + 197 * DH;         // [197][64]

    int tid = threadIdx.x;
    int t1 = 1 + fi * NTOK;

    // cooperative K/V load (float4 granularity)
    for (int idx = tid; idx < 197 * (DH / 4); idx += blockDim.x) {
        int j  = idx >> 4;             // key index 0..196
        int d4 = idx & 15;
        int tok = (j == 0) ? 0 : (t1 + j - 1);
        const float* src = base + (size_t)tok * QKVC;
        *(float4*)(Ks + j * DH + d4 * 4) = *(const float4*)(src + koff + d4 * 4);
        *(float4*)(Vs + j * DH + d4 * 4) = *(const float4*)(src + voff + d4 * 4);
    }
    __syncthreads();

    if (tid < NTOK) {
        int tq = t1 + tid;
        const float* qp = base + (size_t)tq * QKVC + qoff;
        float q[DH];
#pragma unroll
        for (int d = 0; d < DH; d++) q[d] = qp[d] * 0.125f;

        float m = -INFINITY, l = 0.f;
        float o[DH];
#pragma unroll
        for (int d = 0; d < DH; d++) o[d] = 0.f;

        for (int j = 0; j < 197; j++) {
            const float* kr = Ks + j * DH;
            float sdot = 0.f;
#pragma unroll
            for (int d = 0; d < DH; d++) sdot += q[d] * kr[d];
            const float* vr = Vs + j * DH;
            if (sdot > m) {
                float corr = __expf(m - sdot);   // first iter: exp(-inf)=0
                m = sdot;
                l = l * corr + 1.f;
#pragma unroll
                for (int d = 0; d < DH; d++) o[d] = o[d] * corr + vr[d];
            } else {
                float p = __expf(sdot - m);
                l += p;
#pragma unroll
                for (int d = 0; d < DH; d++) o[d] += p * vr[d];
            }
        }
        float inv = 1.f / l;
        float* op = att + ((size_t)bi * NSEQ + tq) * DIM + hi * DH;
#pragma unroll
        for (int d = 0; d < DH; d++) op[d] = o[d] * inv;
    }
}

// ---------------------------------------------------------------------------
extern "C" void kernel_launch(void* const* d_in, const int* in_sizes, int n_in,
                              void* d_out, int out_size) {
    const float* x      = (const float*)d_in[0];
    const float* qkv_w  = (const float*)d_in[1];
    const float* proj_w = (const float*)d_in[2];
    const float* proj_b = (const float*)d_in[3];
    float* out = (float*)d_out;

    float *qkvbuf, *attbuf;
    cudaGetSymbolAddress((void**)&qkvbuf, g_qkv);
    cudaGetSymbolAddress((void**)&attbuf, g_att);

    static const int div_smem = 2 * 197 * DH * (int)sizeof(float);  // 100864
    cudaFuncSetAttribute(div_attn_kernel,
                         cudaFuncAttributeMaxDynamicSharedMemorySize, div_smem);

    // 1) qkv = x @ qkv_w.T   [25096,1024] x [3072,1024]^T
    {
        dim3 grid(QKVC / 128, (MROWS + 127) / 128);
        sgemm_nt<false><<<grid, 256>>>(MROWS, QKVC, DIM, x, qkv_w, nullptr, qkvbuf);
    }

    // 2) attention
    cls_attn_kernel<<<B_ * H_, 256>>>(qkvbuf, attbuf);
    div_attn_kernel<<<B_ * H_ * F_, 256, div_smem>>>(qkvbuf, attbuf);

    // 3) out = att @ proj_w.T + proj_b
    {
        dim3 grid(DIM / 128, (MROWS + 127) / 128);
        sgemm_nt<true><<<grid, 256>>>(MROWS, DIM, DIM, attbuf, proj_w, proj_b, out);
    }
}

// round 2
// speedup vs baseline: 2.1340x; 2.1340x over previous
#include <cuda_runtime.h>
#include <math.h>
#include <stdint.h>

// Problem constants (DividedAttention: b=8, f=16, n=196, dim=1024, H=16)
#define B_    8
#define F_    16
#define NTOK  196
#define NSEQ  3137          // 1 + F_*NTOK
#define DIM   1024
#define H_    16
#define DH    64
#define MROWS (B_ * NSEQ)   // 25096
#define QKVC  (3 * DIM)     // 3072

// Scratch (allowed: __device__ globals)
__device__ float g_qkv[(size_t)MROWS * QKVC];   // [b*N, 3072]
__device__ float g_att[(size_t)MROWS * DIM];    // [b*N, 1024]

// ---------------------------------------------------------------------------
// Helpers
// ---------------------------------------------------------------------------
__device__ __forceinline__ uint32_t cvt_tf32(float x) {
    uint32_t r;
    asm volatile("cvt.rna.tf32.f32 %0, %1;" : "=r"(r) : "f"(x));
    return r;
}

__device__ __forceinline__ void mma_tf32(float* c, const uint32_t* a, const uint32_t* b) {
    asm volatile(
        "mma.sync.aligned.m16n8k8.row.col.f32.tf32.tf32.f32 "
        "{%0,%1,%2,%3}, {%4,%5,%6,%7}, {%8,%9}, {%0,%1,%2,%3};"
        : "+f"(c[0]), "+f"(c[1]), "+f"(c[2]), "+f"(c[3])
        : "r"(a[0]), "r"(a[1]), "r"(a[2]), "r"(a[3]),
          "r"(b[0]), "r"(b[1]));
}

__device__ __forceinline__ void cp_async16(uint32_t smem_addr, const void* gptr) {
    asm volatile("cp.async.cg.shared.global [%0], [%1], 16;\n"
                 :: "r"(smem_addr), "l"(gptr));
}

// ---------------------------------------------------------------------------
// TF32 tensor-core GEMM: C[M,N] = A[M,K] * B[N,K]^T (+ bias).
// A,B row-major, K-contiguous. BM=BN=128, BK=16, 256 threads (8 warps),
// warp tile 32x64 (2x8 m16n8k8), cp.async double buffer.
// ---------------------------------------------------------------------------
#define SA 20   // smem row stride (floats), pad keeps 16B alignment + no conflicts

template <bool BIAS>
__global__ __launch_bounds__(256)
void tgemm_nt(int M, int N, int K,
              const float* __restrict__ A,
              const float* __restrict__ B,
              const float* __restrict__ bias,
              float* __restrict__ C) {
    __shared__ alignas(16) float As[2][128][SA];
    __shared__ alignas(16) float Bs[2][128][SA];

    const int tid  = threadIdx.x;
    const int wid  = tid >> 5;
    const int lane = tid & 31;
    const int row0 = blockIdx.y * 128;
    const int col0 = blockIdx.x * 128;

    const int wm0 = (wid & 3) * 32;    // warp M offset within block tile
    const int wn0 = (wid >> 2) * 64;   // warp N offset

    float acc[2][8][4];
#pragma unroll
    for (int i = 0; i < 2; i++)
#pragma unroll
        for (int j = 0; j < 8; j++)
#pragma unroll
            for (int r = 0; r < 4; r++) acc[i][j][r] = 0.f;

    const int KITERS = K >> 4;

    // load slot -> (row, kchunk): 512 slots of 16B per tile
    const int r_ld0 = (tid * 2) >> 2;
    const int c_ld0 = ((tid * 2) & 3) * 4;
    const int r_ld1 = (tid * 2 + 1) >> 2;
    const int c_ld1 = ((tid * 2 + 1) & 3) * 4;

    auto load_tile = [&](int buf, int it) {
        int k0 = it * 16;
        // A (row-guarded by clamping: garbage rows never stored)
        int ga0 = row0 + r_ld0; if (ga0 >= M) ga0 = M - 1;
        int ga1 = row0 + r_ld1; if (ga1 >= M) ga1 = M - 1;
        cp_async16((uint32_t)__cvta_generic_to_shared(&As[buf][r_ld0][c_ld0]),
                   A + (size_t)ga0 * K + k0 + c_ld0);
        cp_async16((uint32_t)__cvta_generic_to_shared(&As[buf][r_ld1][c_ld1]),
                   A + (size_t)ga1 * K + k0 + c_ld1);
        // B (N is multiple of 128, no guard)
        cp_async16((uint32_t)__cvta_generic_to_shared(&Bs[buf][r_ld0][c_ld0]),
                   B + (size_t)(col0 + r_ld0) * K + k0 + c_ld0);
        cp_async16((uint32_t)__cvta_generic_to_shared(&Bs[buf][r_ld1][c_ld1]),
                   B + (size_t)(col0 + r_ld1) * K + k0 + c_ld1);
        asm volatile("cp.async.commit_group;\n");
    };

    load_tile(0, 0);

    const int g = lane >> 2;     // 0..7
    const int t = lane & 3;      // 0..3

    for (int it = 0; it < KITERS; it++) {
        int buf = it & 1;
        if (it + 1 < KITERS) {
            load_tile(buf ^ 1, it + 1);
            asm volatile("cp.async.wait_group 1;\n");
        } else {
            asm volatile("cp.async.wait_group 0;\n");
        }
        __syncthreads();

#pragma unroll
        for (int ks = 0; ks < 2; ks++) {
            const int kb = ks * 8;
            uint32_t af[2][4], bf[8][2];
#pragma unroll
            for (int mt = 0; mt < 2; mt++) {
                const float* ap = &As[buf][wm0 + mt * 16][kb];
                af[mt][0] = cvt_tf32(ap[(size_t)g * SA + t]);
                af[mt][1] = cvt_tf32(ap[(size_t)(g + 8) * SA + t]);
                af[mt][2] = cvt_tf32(ap[(size_t)g * SA + t + 4]);
                af[mt][3] = cvt_tf32(ap[(size_t)(g + 8) * SA + t + 4]);
            }
#pragma unroll
            for (int nt = 0; nt < 8; nt++) {
                const float* bp = &Bs[buf][wn0 + nt * 8 + g][kb];
                bf[nt][0] = cvt_tf32(bp[t]);
                bf[nt][1] = cvt_tf32(bp[t + 4]);
            }
#pragma unroll
            for (int mt = 0; mt < 2; mt++)
#pragma unroll
                for (int nt = 0; nt < 8; nt++)
                    mma_tf32(acc[mt][nt], af[mt], bf[nt]);
        }
        __syncthreads();
    }

    // Epilogue
#pragma unroll
    for (int mt = 0; mt < 2; mt++) {
        int r_lo = row0 + wm0 + mt * 16 + g;
        int r_hi = r_lo + 8;
#pragma unroll
        for (int nt = 0; nt < 8; nt++) {
            int col = col0 + wn0 + nt * 8 + t * 2;
            float b0 = BIAS ? bias[col] : 0.f;
            float b1 = BIAS ? bias[col + 1] : 0.f;
            if (r_lo < M) {
                float2 v = make_float2(acc[mt][nt][0] + b0, acc[mt][nt][1] + b1);
                *(float2*)(C + (size_t)r_lo * N + col) = v;
            }
            if (r_hi < M) {
                float2 v = make_float2(acc[mt][nt][2] + b0, acc[mt][nt][3] + b1);
                *(float2*)(C + (size_t)r_hi * N + col) = v;
            }
        }
    }
}

// ---------------------------------------------------------------------------
// CLS attention: 1 query (token 0) per (b,h) over all NSEQ keys.
// ---------------------------------------------------------------------------
__global__ __launch_bounds__(256)
void cls_attn_kernel(const float* __restrict__ qkv, float* __restrict__ att) {
    int bh = blockIdx.x;
    int bi = bh >> 4;
    int hi = bh & 15;
    const float* base = qkv + (size_t)bi * NSEQ * QKVC;
    int qoff = hi * DH;
    int koff = DIM + hi * DH;
    int voff = 2 * DIM + hi * DH;

    __shared__ float qs[DH];
    __shared__ float s[NSEQ];
    __shared__ float red[256];

    int tid = threadIdx.x;
    if (tid < DH) qs[tid] = base[qoff + tid];
    __syncthreads();

    const float scale = 0.125f;
    for (int t = tid; t < NSEQ; t += 256) {
        const float* kp = base + (size_t)t * QKVC + koff;
        float acc = 0.f;
#pragma unroll
        for (int d = 0; d < DH; d++) acc += qs[d] * kp[d];
        s[t] = acc * scale;
    }
    __syncthreads();

    float m = -INFINITY;
    for (int t = tid; t < NSEQ; t += 256) m = fmaxf(m, s[t]);
    red[tid] = m;
    __syncthreads();
    for (int st = 128; st > 0; st >>= 1) {
        if (tid < st) red[tid] = fmaxf(red[tid], red[tid + st]);
        __syncthreads();
    }
    m = red[0];
    __syncthreads();

    float l = 0.f;
    for (int t = tid; t < NSEQ; t += 256) {
        float p = __expf(s[t] - m);
        s[t] = p;
        l += p;
    }
    red[tid] = l;
    __syncthreads();
    for (int st = 128; st > 0; st >>= 1) {
        if (tid < st) red[tid] += red[tid + st];
        __syncthreads();
    }
    l = red[0];
    float inv = 1.f / l;

    if (tid < DH) {
        float o = 0.f;
        for (int t = 0; t < NSEQ; t++)
            o += s[t] * base[(size_t)t * QKVC + voff + tid];
        att[(size_t)bi * NSEQ * DIM + hi * DH + tid] = o * inv;
    }
}

// ---------------------------------------------------------------------------
// Divided attention: one block per (b,h,f). 196 queries, 197 keys.
// ---------------------------------------------------------------------------
__global__ __launch_bounds__(256)
void div_attn_kernel(const float* __restrict__ qkv, float* __restrict__ att) {
    int unit = blockIdx.x;
    int bh = unit >> 4;
    int fi = unit & 15;
    int bi = bh >> 4;
    int hi = bh & 15;
    const float* base = qkv + (size_t)bi * NSEQ * QKVC;
    int qoff = hi * DH;
    int koff = DIM + hi * DH;
    int voff = 2 * DIM + hi * DH;

    extern __shared__ float sh[];
    float* Ks = sh;
    float* Vs = sh + 197 * DH;

    int tid = threadIdx.x;
    int t1 = 1 + fi * NTOK;

    for (int idx = tid; idx < 197 * (DH / 4); idx += blockDim.x) {
        int j  = idx >> 4;
        int d4 = idx & 15;
        int tok = (j == 0) ? 0 : (t1 + j - 1);
        const float* src = base + (size_t)tok * QKVC;
        *(float4*)(Ks + j * DH + d4 * 4) = *(const float4*)(src + koff + d4 * 4);
        *(float4*)(Vs + j * DH + d4 * 4) = *(const float4*)(src + voff + d4 * 4);
    }
    __syncthreads();

    if (tid < NTOK) {
        int tq = t1 + tid;
        const float* qp = base + (size_t)tq * QKVC + qoff;
        float q[DH];
#pragma unroll
        for (int d = 0; d < DH; d++) q[d] = qp[d] * 0.125f;

        float m = -INFINITY, l = 0.f;
        float o[DH];
#pragma unroll
        for (int d = 0; d < DH; d++) o[d] = 0.f;

        for (int j = 0; j < 197; j++) {
            const float* kr = Ks + j * DH;
            float sdot = 0.f;
#pragma unroll
            for (int d = 0; d < DH; d++) sdot += q[d] * kr[d];
            const float* vr = Vs + j * DH;
            if (sdot > m) {
                float corr = __expf(m - sdot);
                m = sdot;
                l = l * corr + 1.f;
#pragma unroll
                for (int d = 0; d < DH; d++) o[d] = o[d] * corr + vr[d];
            } else {
                float p = __expf(sdot - m);
                l += p;
#pragma unroll
                for (int d = 0; d < DH; d++) o[d] += p * vr[d];
            }
        }
        float inv = 1.f / l;
        float* op = att + ((size_t)bi * NSEQ + tq) * DIM + hi * DH;
#pragma unroll
        for (int d = 0; d < DH; d++) op[d] = o[d] * inv;
    }
}

// ---------------------------------------------------------------------------
extern "C" void kernel_launch(void* const* d_in, const int* in_sizes, int n_in,
                              void* d_out, int out_size) {
    const float* x      = (const float*)d_in[0];
    const float* qkv_w  = (const float*)d_in[1];
    const float* proj_w = (const float*)d_in[2];
    const float* proj_b = (const float*)d_in[3];
    float* out = (float*)d_out;

    float *qkvbuf, *attbuf;
    cudaGetSymbolAddress((void**)&qkvbuf, g_qkv);
    cudaGetSymbolAddress((void**)&attbuf, g_att);

    static const int div_smem = 2 * 197 * DH * (int)sizeof(float);
    cudaFuncSetAttribute(div_attn_kernel,
                         cudaFuncAttributeMaxDynamicSharedMemorySize, div_smem);

    // 1) qkv = x @ qkv_w.T
    {
        dim3 grid(QKVC / 128, (MROWS + 127) / 128);
        tgemm_nt<false><<<grid, 256>>>(MROWS, QKVC, DIM, x, qkv_w, nullptr, qkvbuf);
    }

    // 2) attention
    cls_attn_kernel<<<B_ * H_, 256>>>(qkvbuf, attbuf);
    div_attn_kernel<<<B_ * H_ * F_, 256, div_smem>>>(qkvbuf, attbuf);

    // 3) out = att @ proj_w.T + proj_b
    {
        dim3 grid(DIM / 128, (MROWS + 127) / 128);
        tgemm_nt<true><<<grid, 256>>>(MROWS, DIM, DIM, attbuf, proj_w, proj_b, out);
    }
}